// round 11
// baseline (speedup 1.0000x reference)
#include <cuda_runtime.h>
#include <cuda_fp16.h>
#include <cstdint>

// ---------------- static scratch ----------------
#define TBITS 21
#define TSIZE (1u << TBITS)
#define TMASK (TSIZE - 1u)
#define EMPTYK 0xFFFFFFFFu
#define MAXE 1050624
#define MAXN 40960
#define DUPCAP 65536

__device__ unsigned int  g_hkey[TSIZE];
__device__ unsigned char g_dupflag[TSIZE];
__device__ int           g_dupid[TSIZE];
__device__ int           g_soe[MAXE];   // pass1: slot of edge; pass2: rev-offset code
__device__ __align__(16) float g_agg[MAXN * 64];
__device__ __align__(16) float g_dupsum[(size_t)DUPCAP * 64];
__device__ int           g_ndup;

// ---------------- helpers ----------------
__device__ __forceinline__ unsigned int mixh(unsigned int x) {
    x ^= x >> 16; x *= 0x7feb352du;
    x ^= x >> 15; x *= 0x846ca68bu;
    x ^= x >> 16; return x;
}

__device__ __forceinline__ void red4(float* p, float4 v) {
    asm volatile("red.global.add.v4.f32 [%0], {%1,%2,%3,%4};"
                 :: "l"(p), "f"(v.x), "f"(v.y), "f"(v.z), "f"(v.w) : "memory");
}

// fp16 split: x -> hi(f16x2) + lo(f16x2 of residual); elem .x in low half
__device__ __forceinline__ void cvt_split(float2 x, uint32_t& hi, uint32_t& lo) {
    __half2 h = __float22half2_rn(x);
    float2 hb = __half22float2(h);
    __half2 l = __floats2half2_rn(x.x - hb.x, x.y - hb.y);
    hi = *(uint32_t*)&h;
    lo = *(uint32_t*)&l;
}

__device__ __forceinline__ void mma16816(float* c, const uint32_t* a,
                                         uint32_t b0, uint32_t b1) {
    asm("mma.sync.aligned.m16n8k16.row.col.f32.f16.f16.f32 "
        "{%0,%1,%2,%3}, {%4,%5,%6,%7}, {%8,%9}, {%0,%1,%2,%3};"
        : "+f"(c[0]), "+f"(c[1]), "+f"(c[2]), "+f"(c[3])
        : "r"(a[0]), "r"(a[1]), "r"(a[2]), "r"(a[3]), "r"(b0), "r"(b1));
}

// ---------------- kernel: hash insert + coalesced v4 aggregation ----------------
// Warp-per-32-edges: each lane CAS-probes its edge (latency-bound chain), then
// the warp sweeps its 32 ef rows with coalesced LDG.128 + red.v4 (2 rows per
// warp-instruction). The two dependency chains overlap in the scheduler.
__global__ __launch_bounds__(256) void k_hashagg(const float* __restrict__ ef,
                                                 const int* __restrict__ esrc,
                                                 const int* __restrict__ edst,
                                                 int nn, int E) {
    const int lane = threadIdx.x & 31;
    const int wid  = threadIdx.x >> 5;
    const int base = (blockIdx.x * 8 + wid) * 32;
    if (base >= E) return;
    const int half = lane >> 4;          // 0: row j, 1: row j+1
    const int col  = (lane & 15) * 4;    // float index within row

    int e = base + lane;
    bool v = e < E;
    int dst = 0;
    if (v) {
        int s = __ldg(&esrc[e]);
        int d = __ldg(&edst[e]);
        dst = d;
        unsigned int key = (unsigned int)s * (unsigned int)nn + (unsigned int)d;
        unsigned int h = mixh(key) & TMASK;
        for (;;) {
            unsigned int prev = atomicCAS(&g_hkey[h], EMPTYK, key);
            if (prev == EMPTYK) break;
            if (prev == key) { g_dupflag[h] = 1; break; }
            h = (h + 1u) & TMASK;
        }
        g_soe[e] = (int)h;
    }

    // coalesced aggregation: 2 rows per warp-instruction
    int nvalid = min(32, E - base);
#pragma unroll 4
    for (int j = 0; j < 32; j += 2) {
        if (j >= nvalid) break;
        int r = j + half;
        int dj = __shfl_sync(0xFFFFFFFFu, dst, r);
        if (r < nvalid) {
            float4 x = *(const float4*)(ef + (size_t)(base + r) * 64 + col);
            red4(g_agg + (size_t)dj * 64 + col, x);
        }
    }
}

// ---------------- kernel: dup claim/acc + rev-offset encode (thread per edge) -------
// Runs after ALL hashing is complete (dupflag final). Touches ef only for the
// ~3% duplicated edges.
__global__ __launch_bounds__(256) void k_dup(const float* __restrict__ ef, int E) {
    int i = blockIdx.x * 256 + threadIdx.x;
    if (i >= E) return;
    int slot = g_soe[i];
    int enc = -1;
    if (g_dupflag[slot]) {
        int d = g_dupid[slot];
        if (d < 0) {
            int my = atomicAdd(&g_ndup, 1);
            int old = atomicCAS(&g_dupid[slot], -1, my);
            d = (old == -1) ? my : old;
        }
        if (d < DUPCAP) {
            enc = d * 256;   // byte offset into g_dupsum
            const float4* row = (const float4*)(ef + (size_t)i * 64);
            float* p = g_dupsum + (size_t)d * 64;
#pragma unroll
            for (int c = 0; c < 16; c++) red4(p + 4 * c, row[c]);
        }
    }
    g_soe[i] = enc;
}

// ---------------- fused: direct-fragment HMMA (R8, unchanged) ----------
// Per warp: M=32 edges x N=64, K=128 (h = [ef | agg[src]-rev]).
// A fragments generated directly from gmem; W fragments in SMEM.
// 3-product fp16 split: xh*wh + xl*wh + xh*wl.
__global__ __launch_bounds__(256, 2) void k_fused_mma(const float* __restrict__ ef,
                                                      const int* __restrict__ esrc,
                                                      const float* __restrict__ W,
                                                      const float* __restrict__ bias,
                                                      float* __restrict__ out, int E) {
    __shared__ uint2 Bf[2][8][8][32];   // [split][kb][nb][lane] = (b0,b1)  32KB

    const int tid  = threadIdx.x;
    const int lane = tid & 31;
    const int wid  = tid >> 5;
    const int q    = lane & 3;     // k-pair selector within fragment
    const int g    = lane >> 2;    // row-in-group

    // Build W fragments (hi & lo splits) in the exact mma B register layout.
    for (int idx = tid; idx < 4096; idx += 256) {
        int split = idx >> 11, kb = (idx >> 8) & 7, nb = (idx >> 5) & 7, L = idx & 31;
        int qq = L & 3, n = nb * 8 + (L >> 2);
        int k0 = kb * 16 + 2 * qq;
        float w00 = W[k0 * 64 + n],       w01 = W[(k0 + 1) * 64 + n];
        float w10 = W[(k0 + 8) * 64 + n], w11 = W[(k0 + 9) * 64 + n];
        uint32_t h0, l0, h1, l1;
        cvt_split(make_float2(w00, w01), h0, l0);
        cvt_split(make_float2(w10, w11), h1, l1);
        Bf[split][kb][nb][L] = (split == 0) ? make_uint2(h0, h1) : make_uint2(l0, l1);
    }
    __syncthreads();

    const int E2 = E >> 1;
    const int nwt = (E + 31) >> 5;

    for (int wt = blockIdx.x * 8 + wid; wt < nwt; wt += gridDim.x * 8) {
        const int e0 = wt * 32;

        const float2* efp[4];
        const float2* srcp[4];
        const float2* revp[4];
        bool val[4];
#pragma unroll
        for (int j = 0; j < 4; j++) {
            int e = e0 + g + 8 * j;
            val[j] = e < E;
            int ec = val[j] ? e : E - 1;
            efp[j]  = (const float2*)(ef + (size_t)ec * 64);
            srcp[j] = (const float2*)(g_agg + (size_t)__ldg(&esrc[ec]) * 64);
            int mm = (ec < E2) ? (ec + E2) : (ec - E2);
            int enc = __ldg(&g_soe[mm]);    // -1 or byte offset into g_dupsum
            revp[j] = (enc >= 0) ? (const float2*)((const char*)g_dupsum + (uint32_t)enc)
                                 : (const float2*)(ef + (size_t)mm * 64);
        }

        float acc[2][8][4];
#pragma unroll
        for (int mb = 0; mb < 2; mb++)
#pragma unroll
            for (int nb = 0; nb < 8; nb++)
#pragma unroll
                for (int c = 0; c < 4; c++) acc[mb][nb][c] = 0.f;

#pragma unroll
        for (int kb = 0; kb < 8; kb++) {
            uint32_t ah[2][4], al[2][4];
#pragma unroll
            for (int mb = 0; mb < 2; mb++) {
#pragma unroll
                for (int j2 = 0; j2 < 2; j2++) {
                    int j = mb * 2 + j2;
                    float2 x0, x1;
                    if (kb < 4) {
                        x0 = efp[j][kb * 8 + q];
                        x1 = efp[j][kb * 8 + q + 4];
                    } else {
                        int kk = kb - 4;
                        float2 a0 = srcp[j][kk * 8 + q];
                        float2 r0 = revp[j][kk * 8 + q];
                        float2 a1 = srcp[j][kk * 8 + q + 4];
                        float2 r1 = revp[j][kk * 8 + q + 4];
                        x0 = make_float2(a0.x - r0.x, a0.y - r0.y);
                        x1 = make_float2(a1.x - r1.x, a1.y - r1.y);
                    }
                    cvt_split(x0, ah[mb][0 + j2], al[mb][0 + j2]);
                    cvt_split(x1, ah[mb][2 + j2], al[mb][2 + j2]);
                }
            }
#pragma unroll
            for (int nb = 0; nb < 8; nb++) {
                uint2 bh = Bf[0][kb][nb][lane];
                uint2 bl = Bf[1][kb][nb][lane];
#pragma unroll
                for (int mb = 0; mb < 2; mb++) {
                    mma16816(acc[mb][nb], ah[mb], bh.x, bh.y);   // xh*wh
                    mma16816(acc[mb][nb], al[mb], bh.x, bh.y);   // xl*wh
                    mma16816(acc[mb][nb], ah[mb], bl.x, bl.y);   // xh*wl
                }
            }
        }

        // epilogue: bias + relu, coalesced-sector stores
#pragma unroll
        for (int mb = 0; mb < 2; mb++) {
#pragma unroll
            for (int nb = 0; nb < 8; nb++) {
                int col = nb * 8 + 2 * q;
                float2 bv = __ldg((const float2*)(bias + col));
                if (val[mb * 2]) {
                    float2 o = make_float2(fmaxf(acc[mb][nb][0] + bv.x, 0.f),
                                           fmaxf(acc[mb][nb][1] + bv.y, 0.f));
                    *(float2*)(out + (size_t)(e0 + mb * 16 + g) * 64 + col) = o;
                }
                if (val[mb * 2 + 1]) {
                    float2 o = make_float2(fmaxf(acc[mb][nb][2] + bv.x, 0.f),
                                           fmaxf(acc[mb][nb][3] + bv.y, 0.f));
                    *(float2*)(out + (size_t)(e0 + mb * 16 + g + 8) * 64 + col) = o;
                }
            }
        }
    }
}

// ---------------- launch ----------------
extern "C" void kernel_launch(void* const* d_in, const int* in_sizes, int n_in,
                              void* d_out, int out_size) {
    const float* ef   = (const float*)d_in[0];
    const int*   esrc = (const int*)d_in[1];
    const int*   edst = (const int*)d_in[2];
    const float* W    = (const float*)d_in[5];
    const float* bias = (const float*)d_in[6];
    float* out = (float*)d_out;

    int E  = in_sizes[1];
    int nn = in_sizes[3];

    void *p_hkey, *p_flag, *p_agg, *p_dupid, *p_dupsum, *p_ndup;
    cudaGetSymbolAddress(&p_hkey,   g_hkey);
    cudaGetSymbolAddress(&p_flag,   g_dupflag);
    cudaGetSymbolAddress(&p_agg,    g_agg);
    cudaGetSymbolAddress(&p_dupid,  g_dupid);
    cudaGetSymbolAddress(&p_dupsum, g_dupsum);
    cudaGetSymbolAddress(&p_ndup,   g_ndup);

    cudaMemsetAsync(p_hkey,   0xFF, (size_t)TSIZE * 4);
    cudaMemsetAsync(p_flag,   0x00, (size_t)TSIZE);
    cudaMemsetAsync(p_agg,    0x00, (size_t)nn * 64 * 4);
    cudaMemsetAsync(p_dupid,  0xFF, (size_t)TSIZE * 4);
    cudaMemsetAsync(p_dupsum, 0x00, (size_t)DUPCAP * 64 * 4);
    cudaMemsetAsync(p_ndup,   0x00, 4);

    k_hashagg<<<(E + 255) / 256, 256>>>(ef, esrc, edst, nn, E);
    k_dup<<<(E + 255) / 256, 256>>>(ef, E);

    k_fused_mma<<<296, 256>>>(ef, esrc, W, bias, out, E);
}

// round 12
// speedup vs baseline: 1.0403x; 1.0403x over previous
#include <cuda_runtime.h>
#include <cuda_fp16.h>
#include <cstdint>

// ---------------- static scratch ----------------
#define TBITS 21
#define TSIZE (1u << TBITS)
#define TMASK (TSIZE - 1u)
#define EMPTYK 0xFFFFFFFFu
#define MAXE 1050624
#define MAXN 40960
#define DUPCAP 65536

__device__ unsigned int  g_hkey[TSIZE];
__device__ unsigned char g_dupflag[TSIZE];
__device__ int           g_dupid[TSIZE];
__device__ int           g_soe[MAXE];   // pass1: slot of edge; pass2: rev-offset code
__device__ __align__(16) float g_agg[MAXN * 64];
__device__ __align__(16) float g_dupsum[(size_t)DUPCAP * 64];
__device__ int           g_ndup;

// ---------------- helpers ----------------
__device__ __forceinline__ unsigned int mixh(unsigned int x) {
    x ^= x >> 16; x *= 0x7feb352du;
    x ^= x >> 15; x *= 0x846ca68bu;
    x ^= x >> 16; return x;
}

__device__ __forceinline__ void red4(float* p, float4 v) {
    asm volatile("red.global.add.v4.f32 [%0], {%1,%2,%3,%4};"
                 :: "l"(p), "f"(v.x), "f"(v.y), "f"(v.z), "f"(v.w) : "memory");
}

// fp16 split: x -> hi(f16x2) + lo(f16x2 of residual); elem .x in low half
__device__ __forceinline__ void cvt_split(float2 x, uint32_t& hi, uint32_t& lo) {
    __half2 h = __float22half2_rn(x);
    float2 hb = __half22float2(h);
    __half2 l = __floats2half2_rn(x.x - hb.x, x.y - hb.y);
    hi = *(uint32_t*)&h;
    lo = *(uint32_t*)&l;
}

__device__ __forceinline__ void mma16816(float* c, const uint32_t* a,
                                         uint32_t b0, uint32_t b1) {
    asm("mma.sync.aligned.m16n8k16.row.col.f32.f16.f16.f32 "
        "{%0,%1,%2,%3}, {%4,%5,%6,%7}, {%8,%9}, {%0,%1,%2,%3};"
        : "+f"(c[0]), "+f"(c[1]), "+f"(c[2]), "+f"(c[3])
        : "r"(a[0]), "r"(a[1]), "r"(a[2]), "r"(a[3]), "r"(b0), "r"(b1));
}

// ---------------- kernel: hash insert + coalesced v4 aggregation ----------------
__global__ __launch_bounds__(256) void k_hashagg(const float* __restrict__ ef,
                                                 const int* __restrict__ esrc,
                                                 const int* __restrict__ edst,
                                                 int nn, int E) {
    const int lane = threadIdx.x & 31;
    const int wid  = threadIdx.x >> 5;
    const int base = (blockIdx.x * 8 + wid) * 32;
    if (base >= E) return;
    const int half = lane >> 4;          // 0: row j, 1: row j+1
    const int col  = (lane & 15) * 4;    // float index within row

    int e = base + lane;
    bool v = e < E;
    int dst = 0;
    if (v) {
        int s = __ldg(&esrc[e]);
        int d = __ldg(&edst[e]);
        dst = d;
        unsigned int key = (unsigned int)s * (unsigned int)nn + (unsigned int)d;
        unsigned int h = mixh(key) & TMASK;
        for (;;) {
            unsigned int prev = atomicCAS(&g_hkey[h], EMPTYK, key);
            if (prev == EMPTYK) break;
            if (prev == key) { g_dupflag[h] = 1; break; }
            h = (h + 1u) & TMASK;
        }
        g_soe[e] = (int)h;
    }

    int nvalid = min(32, E - base);
#pragma unroll 4
    for (int j = 0; j < 32; j += 2) {
        if (j >= nvalid) break;
        int r = j + half;
        int dj = __shfl_sync(0xFFFFFFFFu, dst, r);
        if (r < nvalid) {
            float4 x = *(const float4*)(ef + (size_t)(base + r) * 64 + col);
            red4(g_agg + (size_t)dj * 64 + col, x);
        }
    }
}

// ---------------- kernel: dup claim/acc + rev-offset encode (thread per edge) -------
__global__ __launch_bounds__(256) void k_dup(const float* __restrict__ ef, int E) {
    int i = blockIdx.x * 256 + threadIdx.x;
    if (i >= E) return;
    int slot = g_soe[i];
    int enc = -1;
    if (g_dupflag[slot]) {
        int d = g_dupid[slot];
        if (d < 0) {
            int my = atomicAdd(&g_ndup, 1);
            int old = atomicCAS(&g_dupid[slot], -1, my);
            d = (old == -1) ? my : old;
        }
        if (d < DUPCAP) {
            enc = d * 256;   // byte offset into g_dupsum
            const float4* row = (const float4*)(ef + (size_t)i * 64);
            float* p = g_dupsum + (size_t)d * 64;
#pragma unroll
            for (int c = 0; c < 16; c++) red4(p + 4 * c, row[c]);
        }
    }
    g_soe[i] = enc;
}

// ---------------- fused: direct-fragment HMMA, K-permuted float4 loads ----------
// Per warp: M=32 edges x N=64, K=128 (h = [ef | agg[src]-rev]).
// K-permute within each 16-k block: mma k-slots {2q,2q+1,2q+8,2q+9} <- data
// cols kb*16+4q+{0,1,2,3} (applied identically to A loads and W table), so
// each thread's A fragment is ONE float4 load. 3-product split as before.
__global__ __launch_bounds__(256, 2) void k_fused_mma(const float* __restrict__ ef,
                                                      const int* __restrict__ esrc,
                                                      const float* __restrict__ W,
                                                      const float* __restrict__ bias,
                                                      float* __restrict__ out, int E) {
    __shared__ uint2 Bf[2][8][8][32];   // [split][kb][nb][lane] = (b0,b1)  32KB

    const int tid  = threadIdx.x;
    const int lane = tid & 31;
    const int wid  = tid >> 5;
    const int q    = lane & 3;     // k-quad selector within fragment
    const int g    = lane >> 2;    // row-in-group

    // W fragments with K-permutation: slots (2q,2q+1) <- data k0,k0+1;
    // slots (2q+8,2q+9) <- data k0+2,k0+3, where k0 = kb*16 + 4q.
    for (int idx = tid; idx < 4096; idx += 256) {
        int split = idx >> 11, kb = (idx >> 8) & 7, nb = (idx >> 5) & 7, L = idx & 31;
        int qq = L & 3, n = nb * 8 + (L >> 2);
        int k0 = kb * 16 + 4 * qq;
        float w00 = W[k0 * 64 + n],       w01 = W[(k0 + 1) * 64 + n];
        float w10 = W[(k0 + 2) * 64 + n], w11 = W[(k0 + 3) * 64 + n];
        uint32_t h0, l0, h1, l1;
        cvt_split(make_float2(w00, w01), h0, l0);
        cvt_split(make_float2(w10, w11), h1, l1);
        Bf[split][kb][nb][L] = (split == 0) ? make_uint2(h0, h1) : make_uint2(l0, l1);
    }
    __syncthreads();

    const int E2 = E >> 1;
    const int nwt = (E + 31) >> 5;

    for (int wt = blockIdx.x * 8 + wid; wt < nwt; wt += gridDim.x * 8) {
        const int e0 = wt * 32;

        const float4* efp[4];
        const float4* srcp[4];
        const float4* revp[4];
        bool val[4];
#pragma unroll
        for (int j = 0; j < 4; j++) {
            int e = e0 + g + 8 * j;
            val[j] = e < E;
            int ec = val[j] ? e : E - 1;
            efp[j]  = (const float4*)(ef + (size_t)ec * 64);
            srcp[j] = (const float4*)(g_agg + (size_t)__ldg(&esrc[ec]) * 64);
            int mm = (ec < E2) ? (ec + E2) : (ec - E2);
            int enc = __ldg(&g_soe[mm]);    // -1 or byte offset into g_dupsum
            revp[j] = (enc >= 0) ? (const float4*)((const char*)g_dupsum + (uint32_t)enc)
                                 : (const float4*)(ef + (size_t)mm * 64);
        }

        float acc[2][8][4];
#pragma unroll
        for (int mb = 0; mb < 2; mb++)
#pragma unroll
            for (int nb = 0; nb < 8; nb++)
#pragma unroll
                for (int c = 0; c < 4; c++) acc[mb][nb][c] = 0.f;

#pragma unroll
        for (int kb = 0; kb < 8; kb++) {
            uint32_t ah[2][4], al[2][4];
#pragma unroll
            for (int mb = 0; mb < 2; mb++) {
#pragma unroll
                for (int j2 = 0; j2 < 2; j2++) {
                    int j = mb * 2 + j2;
                    float4 x;
                    if (kb < 4) {
                        x = efp[j][kb * 4 + q];
                    } else {
                        int kk = kb - 4;
                        float4 a = srcp[j][kk * 4 + q];
                        float4 r = revp[j][kk * 4 + q];
                        x = make_float4(a.x - r.x, a.y - r.y, a.z - r.z, a.w - r.w);
                    }
                    cvt_split(make_float2(x.x, x.y), ah[mb][0 + j2], al[mb][0 + j2]);
                    cvt_split(make_float2(x.z, x.w), ah[mb][2 + j2], al[mb][2 + j2]);
                }
            }
#pragma unroll
            for (int nb = 0; nb < 8; nb++) {
                uint2 bh = Bf[0][kb][nb][lane];
                uint2 bl = Bf[1][kb][nb][lane];
#pragma unroll
                for (int mb = 0; mb < 2; mb++) {
                    mma16816(acc[mb][nb], ah[mb], bh.x, bh.y);   // xh*wh
                    mma16816(acc[mb][nb], al[mb], bh.x, bh.y);   // xl*wh
                    mma16816(acc[mb][nb], ah[mb], bl.x, bl.y);   // xh*wl
                }
            }
        }

        // epilogue: bias + relu, coalesced-sector stores
#pragma unroll
        for (int mb = 0; mb < 2; mb++) {
#pragma unroll
            for (int nb = 0; nb < 8; nb++) {
                int col = nb * 8 + 2 * q;
                float2 bv = __ldg((const float2*)(bias + col));
                if (val[mb * 2]) {
                    float2 o = make_float2(fmaxf(acc[mb][nb][0] + bv.x, 0.f),
                                           fmaxf(acc[mb][nb][1] + bv.y, 0.f));
                    *(float2*)(out + (size_t)(e0 + mb * 16 + g) * 64 + col) = o;
                }
                if (val[mb * 2 + 1]) {
                    float2 o = make_float2(fmaxf(acc[mb][nb][2] + bv.x, 0.f),
                                           fmaxf(acc[mb][nb][3] + bv.y, 0.f));
                    *(float2*)(out + (size_t)(e0 + mb * 16 + g + 8) * 64 + col) = o;
                }
            }
        }
    }
}

// ---------------- launch ----------------
extern "C" void kernel_launch(void* const* d_in, const int* in_sizes, int n_in,
                              void* d_out, int out_size) {
    const float* ef   = (const float*)d_in[0];
    const int*   esrc = (const int*)d_in[1];
    const int*   edst = (const int*)d_in[2];
    const float* W    = (const float*)d_in[5];
    const float* bias = (const float*)d_in[6];
    float* out = (float*)d_out;

    int E  = in_sizes[1];
    int nn = in_sizes[3];

    void *p_hkey, *p_flag, *p_agg, *p_dupid, *p_dupsum, *p_ndup;
    cudaGetSymbolAddress(&p_hkey,   g_hkey);
    cudaGetSymbolAddress(&p_flag,   g_dupflag);
    cudaGetSymbolAddress(&p_agg,    g_agg);
    cudaGetSymbolAddress(&p_dupid,  g_dupid);
    cudaGetSymbolAddress(&p_dupsum, g_dupsum);
    cudaGetSymbolAddress(&p_ndup,   g_ndup);

    cudaMemsetAsync(p_hkey,   0xFF, (size_t)TSIZE * 4);
    cudaMemsetAsync(p_flag,   0x00, (size_t)TSIZE);
    cudaMemsetAsync(p_agg,    0x00, (size_t)nn * 64 * 4);
    cudaMemsetAsync(p_dupid,  0xFF, (size_t)TSIZE * 4);
    cudaMemsetAsync(p_dupsum, 0x00, (size_t)DUPCAP * 64 * 4);
    cudaMemsetAsync(p_ndup,   0x00, 4);

    k_hashagg<<<(E + 255) / 256, 256>>>(ef, esrc, edst, nn, E);
    k_dup<<<(E + 255) / 256, 256>>>(ef, E);

    k_fused_mma<<<296, 256>>>(ef, esrc, W, bias, out, E);
}